// round 3
// baseline (speedup 1.0000x reference)
#include <cuda_runtime.h>
#include <math.h>

#define CH   256
#define NPIX 3136
#define NB   32

// Scratch (device globals — no allocation allowed in kernel_launch).
// Referenced directly by name in device code; kernel_launch makes no
// runtime API calls besides kernel launches (strict graph-capture safety).
__device__ float g_q[(size_t)NB * CH * NPIX];   // conv1 output (shared q=k=v)
__device__ float g_t[(size_t)NB * CH * NPIX];   // attn @ q
__device__ float g_s[(size_t)NB * CH * CH];     // scores / attn

// ---------------------------------------------------------------------------
// NN GEMM: C_b[256, NPIX] = A_b[256,256] * B_b[256, NPIX] (+ bias)
// 128x128 tile, BK=8, 256 threads, 8x8 microtile.
// MODE 0: A=W (param),   B=x (param),  C=g_q,  +bias
// MODE 1: A=g_s (batched) B=g_q,       C=g_t,  no bias
// MODE 2: A=W (param),   B=g_t,        C=out (param), +bias
// ---------------------------------------------------------------------------
template<int MODE>
__global__ __launch_bounds__(256, 2)
void gemm_nn(const float* __restrict__ Wp,
             const float* __restrict__ Xp,
             float* __restrict__ Op,
             const float* __restrict__ bias)
{
    const int bz = blockIdx.z;

    const float* A;
    const float* B;
    float*       Cc;
    if (MODE == 0) {
        A  = Wp;
        B  = Xp  + (long)bz * (long)CH * NPIX;
        Cc = g_q + (long)bz * (long)CH * NPIX;
    } else if (MODE == 1) {
        A  = g_s + (long)bz * (long)CH * CH;
        B  = g_q + (long)bz * (long)CH * NPIX;
        Cc = g_t + (long)bz * (long)CH * NPIX;
    } else {
        A  = Wp;
        B  = g_t + (long)bz * (long)CH * NPIX;
        Cc = Op  + (long)bz * (long)CH * NPIX;
    }

    const int n0 = blockIdx.x * 128;
    const int m0 = blockIdx.y * 128;
    const int tid = threadIdx.x;

    __shared__ float As[8][128];
    __shared__ float Bs[8][128];

    const int aRow = tid >> 1;            // 0..127
    const int aCol = (tid & 1) << 2;      // 0 or 4
    const int bRow = tid >> 5;            // 0..7
    const int bCol = (tid & 31) << 2;     // 0..124
    const int tx = tid & 15;
    const int ty = tid >> 4;

    float acc[8][8];
#pragma unroll
    for (int i = 0; i < 8; i++)
#pragma unroll
        for (int j = 0; j < 8; j++) acc[i][j] = 0.f;

    const bool bvalid = (n0 + bCol) < NPIX;   // NPIX % 4 == 0, float4 never straddles

    for (int k0 = 0; k0 < CH; k0 += 8) {
        float4 av = *(const float4*)(A + (long)(m0 + aRow) * CH + k0 + aCol);
        float4 bv = make_float4(0.f, 0.f, 0.f, 0.f);
        if (bvalid)
            bv = *(const float4*)(B + (long)(k0 + bRow) * NPIX + n0 + bCol);

        As[aCol + 0][aRow] = av.x;
        As[aCol + 1][aRow] = av.y;
        As[aCol + 2][aRow] = av.z;
        As[aCol + 3][aRow] = av.w;
        *(float4*)&Bs[bRow][bCol] = bv;
        __syncthreads();

#pragma unroll
        for (int k = 0; k < 8; k++) {
            float a[8], bb[8];
            *(float4*)&a[0]  = *(const float4*)&As[k][ty * 4];
            *(float4*)&a[4]  = *(const float4*)&As[k][64 + ty * 4];
            *(float4*)&bb[0] = *(const float4*)&Bs[k][tx * 4];
            *(float4*)&bb[4] = *(const float4*)&Bs[k][64 + tx * 4];
#pragma unroll
            for (int i = 0; i < 8; i++)
#pragma unroll
                for (int j = 0; j < 8; j++)
                    acc[i][j] += a[i] * bb[j];
        }
        __syncthreads();
    }

#pragma unroll
    for (int i = 0; i < 8; i++) {
        const int m = m0 + ((i < 4) ? (ty * 4 + i) : (64 + ty * 4 + (i - 4)));
        const float bv = (MODE == 1) ? 0.f : bias[m];
#pragma unroll
        for (int jj = 0; jj < 2; jj++) {
            const int c = n0 + ((jj == 0) ? (tx * 4) : (64 + tx * 4));
            if (c < NPIX) {
                float4 v;
                v.x = acc[i][jj * 4 + 0] + bv;
                v.y = acc[i][jj * 4 + 1] + bv;
                v.z = acc[i][jj * 4 + 2] + bv;
                v.w = acc[i][jj * 4 + 3] + bv;
                *(float4*)(Cc + (long)m * NPIX + c) = v;
            }
        }
    }
}

// ---------------------------------------------------------------------------
// NT GEMM (scores): g_s_b[256,256] = g_q_b[256,NPIX] * g_q_b^T  (K = NPIX)
// 64x64 tile, BK=16, 256 threads, 4x4 microtile
// ---------------------------------------------------------------------------
__global__ __launch_bounds__(256, 4)
void gemm_nt_scores()
{
    const int bz = blockIdx.z;
    const float* Qb = g_q + (long)bz * (long)CH * NPIX;
    float*       Sb = g_s + (long)bz * (long)CH * CH;

    const int n0 = blockIdx.x * 64;
    const int m0 = blockIdx.y * 64;
    const int tid = threadIdx.x;

    __shared__ float As[16][68];   // [k][m], pad 68 keeps float4 alignment
    __shared__ float Bs[16][68];   // [k][n]

    const int lRow = tid >> 2;            // 0..63
    const int lCol = (tid & 3) << 2;      // 0,4,8,12
    const int tx = tid & 15;
    const int ty = tid >> 4;

    float acc[4][4];
#pragma unroll
    for (int i = 0; i < 4; i++)
#pragma unroll
        for (int j = 0; j < 4; j++) acc[i][j] = 0.f;

    for (int k0 = 0; k0 < NPIX; k0 += 16) {
        float4 av = *(const float4*)(Qb + (long)(m0 + lRow) * NPIX + k0 + lCol);
        float4 bv = *(const float4*)(Qb + (long)(n0 + lRow) * NPIX + k0 + lCol);
        As[lCol + 0][lRow] = av.x;
        As[lCol + 1][lRow] = av.y;
        As[lCol + 2][lRow] = av.z;
        As[lCol + 3][lRow] = av.w;
        Bs[lCol + 0][lRow] = bv.x;
        Bs[lCol + 1][lRow] = bv.y;
        Bs[lCol + 2][lRow] = bv.z;
        Bs[lCol + 3][lRow] = bv.w;
        __syncthreads();

#pragma unroll
        for (int k = 0; k < 16; k++) {
            float a[4], bb[4];
            *(float4*)a  = *(const float4*)&As[k][ty * 4];
            *(float4*)bb = *(const float4*)&Bs[k][tx * 4];
#pragma unroll
            for (int i = 0; i < 4; i++)
#pragma unroll
                for (int j = 0; j < 4; j++)
                    acc[i][j] += a[i] * bb[j];
        }
        __syncthreads();
    }

#pragma unroll
    for (int i = 0; i < 4; i++) {
        const int m = m0 + ty * 4 + i;
        float4 v;
        v.x = acc[i][0]; v.y = acc[i][1]; v.z = acc[i][2]; v.w = acc[i][3];
        *(float4*)(Sb + (long)m * CH + n0 + tx * 4) = v;
    }
}

// ---------------------------------------------------------------------------
// Row softmax over 256-wide rows of g_s, one block (256 threads) per row
// ---------------------------------------------------------------------------
__global__ void softmax256()
{
    const long row = blockIdx.x;
    float* p = g_s + row * CH;
    const int t = threadIdx.x;

    __shared__ float redm[8];
    __shared__ float reds[8];

    float v = p[t];

    float m = v;
#pragma unroll
    for (int o = 16; o > 0; o >>= 1)
        m = fmaxf(m, __shfl_xor_sync(0xffffffffu, m, o));
    if ((t & 31) == 0) redm[t >> 5] = m;
    __syncthreads();
    float mx = redm[0];
#pragma unroll
    for (int i = 1; i < 8; i++) mx = fmaxf(mx, redm[i]);

    float e = __expf(v - mx);

    float s = e;
#pragma unroll
    for (int o = 16; o > 0; o >>= 1)
        s += __shfl_xor_sync(0xffffffffu, s, o);
    if ((t & 31) == 0) reds[t >> 5] = s;
    __syncthreads();
    float sum = reds[0];
#pragma unroll
    for (int i = 1; i < 8; i++) sum += reds[i];

    p[t] = e / sum;
}

// ---------------------------------------------------------------------------
extern "C" void kernel_launch(void* const* d_in, const int* in_sizes, int n_in,
                              void* d_out, int out_size)
{
    const float* x    = (const float*)d_in[0];  // [32,256,56,56]
    const float* W    = (const float*)d_in[1];  // [256,256]  W[o,c]
    const float* bias = (const float*)d_in[2];  // [256]
    float* out = (float*)d_out;                 // [32,256,56,56]

    const dim3 gNN((NPIX + 127) / 128, CH / 128, NB);   // 25 x 2 x 32
    const dim3 gNT(CH / 64, CH / 64, NB);               // 4 x 4 x 32

    // 1) g_q = conv1x1(x) = W @ x_b + bias
    gemm_nn<0><<<gNN, 256>>>(W, x, nullptr, bias);
    // 2) g_s = q @ q^T per batch
    gemm_nt_scores<<<gNT, 256>>>();
    // 3) softmax along last dim (in place on g_s)
    softmax256<<<NB * CH, 256>>>();
    // 4) g_t = attn @ q
    gemm_nn<1><<<gNN, 256>>>(nullptr, nullptr, nullptr, nullptr);
    // 5) out = conv1x1(g_t) = W @ g_t + bias
    gemm_nn<2><<<gNN, 256>>>(W, nullptr, out, bias);
}

// round 5
// speedup vs baseline: 1.9925x; 1.9925x over previous
#include <cuda_runtime.h>
#include <cuda_bf16.h>
#include <cstdint>

#define CH    256
#define NPIX  3136
#define NP    3200
#define NB    32

// ---------------------------------------------------------------------------
// Device scratch (no allocations). All row-major, no transposed copies needed.
// ---------------------------------------------------------------------------
__device__ __nv_bfloat16 g_Wh[CH * CH], g_Wl[CH * CH];
__device__ __nv_bfloat16 g_Xh[(size_t)NB * CH * NP], g_Xl[(size_t)NB * CH * NP];  // x split
__device__ __nv_bfloat16 g_qh[(size_t)NB * CH * NP], g_ql[(size_t)NB * CH * NP];  // q split
__device__ float         g_S [(size_t)NB * CH * CH];                              // scores
__device__ __nv_bfloat16 g_Ah[(size_t)NB * CH * CH], g_Al[(size_t)NB * CH * CH];  // attn split
__device__ __nv_bfloat16 g_th[(size_t)NB * CH * NP], g_tl[(size_t)NB * CH * NP];  // t split

// ---------------------------------------------------------------------------
// PTX helpers (sm_80+ features only: mma.sync, ldmatrix, cp.async)
// ---------------------------------------------------------------------------
__device__ __forceinline__ void ldsm4(uint32_t* r, uint32_t a) {
    asm volatile("ldmatrix.sync.aligned.m8n8.x4.shared.b16 {%0,%1,%2,%3}, [%4];"
                 : "=r"(r[0]), "=r"(r[1]), "=r"(r[2]), "=r"(r[3]) : "r"(a));
}
__device__ __forceinline__ void ldsm4t(uint32_t* r, uint32_t a) {
    asm volatile("ldmatrix.sync.aligned.m8n8.x4.trans.shared.b16 {%0,%1,%2,%3}, [%4];"
                 : "=r"(r[0]), "=r"(r[1]), "=r"(r[2]), "=r"(r[3]) : "r"(a));
}
__device__ __forceinline__ void mma_bf16(float* c, const uint32_t* a, const uint32_t* b) {
    asm volatile("mma.sync.aligned.m16n8k16.row.col.f32.bf16.bf16.f32 "
                 "{%0,%1,%2,%3}, {%4,%5,%6,%7}, {%8,%9}, {%0,%1,%2,%3};"
                 : "+f"(c[0]), "+f"(c[1]), "+f"(c[2]), "+f"(c[3])
                 : "r"(a[0]), "r"(a[1]), "r"(a[2]), "r"(a[3]), "r"(b[0]), "r"(b[1]));
}
__device__ __forceinline__ void cpa(uint32_t d, const void* s) {
    uint64_t g;
    asm("cvta.to.global.u64 %0, %1;" : "=l"(g) : "l"(s));
    asm volatile("cp.async.cg.shared.global [%0], [%1], 16;" :: "r"(d), "l"(g) : "memory");
}
#define CP_COMMIT asm volatile("cp.async.commit_group;" ::: "memory")
#define CP_WAIT1  asm volatile("cp.async.wait_group 1;" ::: "memory")
#define CP_WAIT0  asm volatile("cp.async.wait_group 0;" ::: "memory")

__device__ __forceinline__ uint32_t smem_u32(const void* p) {
    uint32_t a;
    asm("{ .reg .u64 t; cvta.to.shared.u64 t, %1; cvt.u32.u64 %0, t; }" : "=r"(a) : "l"(p));
    return a;
}
__device__ __forceinline__ void split2(float v, __nv_bfloat16& h, __nv_bfloat16& l) {
    h = __float2bfloat16(v);
    l = __float2bfloat16(v - __bfloat162float(h));
}

// ---------------------------------------------------------------------------
// Unified split-bf16 tensor-core GEMM.
//   GID 1: q   = W @ x   (+bias, zero n-pads)   M=256 N=NP  K=256   B trans
//   GID 2: S   = q @ q^T  (fp32 out)            M=256 N=256 K=NP    B non-trans
//   GID 4: t   = attn @ q                       M=256 N=NP  K=256   B trans
//   GID 5: out = W @ t   (+bias, fp32 out)      M=256 N=NP  K=256   B trans
// BM=128 BN=128 BK=16, 256 thr (8 warps 2x4), warp tile 64x32.
// Static SMEM 48KB: 2 stages x (Ah|Al 6144 ea @stride 24el, Bh|Bl @BHO).
// ---------------------------------------------------------------------------
#define STG   24576
#define AHO   0
#define ALOFF 6144
#define BHO   12288

template<int GID>
__global__ __launch_bounds__(256)
void gemm_mma(const float* __restrict__ bias, float* __restrict__ outF)
{
    constexpr int  KF     = (GID == 2) ? NP : CH;
    constexpr bool BTRANS = (GID != 2);
    constexpr int  NC     = KF / 16;
    constexpr int  BLOFF  = BTRANS ? 4352 : 6144;   // B tile bytes per h/l

    __shared__ __align__(256) char smem[49152];
    const uint32_t sb = smem_u32(smem);

    const int tid  = threadIdx.x;
    const int lane = tid & 31;
    const int wid  = tid >> 5;
    const int wm   = (wid >> 2) * 64;
    const int wn   = (wid & 3) * 32;
    const int bz   = blockIdx.z;
    const int n0   = blockIdx.x * 128;
    const int m0   = blockIdx.y * 128;

    const __nv_bfloat16 *Ah, *Al, *Bh, *Bl;
    if (GID == 1) {
        Ah = g_Wh;  Al = g_Wl;
        Bh = g_Xh + (size_t)bz * CH * NP;  Bl = g_Xl + (size_t)bz * CH * NP;
    } else if (GID == 2) {
        Ah = g_qh + (size_t)bz * CH * NP;  Al = g_ql + (size_t)bz * CH * NP;
        Bh = Ah;  Bl = Al;
    } else if (GID == 4) {
        Ah = g_Ah + (size_t)bz * CH * CH;  Al = g_Al + (size_t)bz * CH * CH;
        Bh = g_qh + (size_t)bz * CH * NP;  Bl = g_ql + (size_t)bz * CH * NP;
    } else {
        Ah = g_Wh;  Al = g_Wl;
        Bh = g_th + (size_t)bz * CH * NP;  Bl = g_tl + (size_t)bz * CH * NP;
    }

    float acc[4][4][4];
#pragma unroll
    for (int mi = 0; mi < 4; mi++)
#pragma unroll
        for (int ni = 0; ni < 4; ni++)
#pragma unroll
            for (int r = 0; r < 4; r++) acc[mi][ni][r] = 0.f;

    // -- stage loader: 4 x cp.async(16B) per thread --------------------------
    auto load_stage = [&](int buf, int k0) {
        const uint32_t base = sb + buf * STG;
        {   // A: 128 rows x 16el (2 chunks), stride 24el(48B)
            const int row = tid >> 1, g = tid & 1;
            const uint32_t d = base + AHO + row * 48 + g * 16;
            const size_t  so = (size_t)(m0 + row) * KF + k0 + g * 8;
            cpa(d,          Ah + so);
            cpa(d + ALOFF,  Al + so);
        }
        if (BTRANS) {  // B: [k=16][n=128] rows, stride 136el(272B)
            const int row = tid >> 4, g = tid & 15;
            const uint32_t d = base + BHO + row * 272 + g * 16;
            const size_t  so = (size_t)(k0 + row) * NP + n0 + g * 8;
            cpa(d,          Bh + so);
            cpa(d + BLOFF,  Bl + so);
        } else {       // B: [n=128][k=16] rows, stride 24el(48B)
            const int row = tid >> 1, g = tid & 1;
            const uint32_t d = base + BHO + row * 48 + g * 16;
            const size_t  so = (size_t)(n0 + row) * NP + k0 + g * 8;
            cpa(d,          Bh + so);
            cpa(d + BLOFF,  Bl + so);
        }
        CP_COMMIT;
    };

    // ldmatrix base offsets (element units -> bytes)
    const uint32_t aBase = ((uint32_t)(wm + (lane & 15)) * 24 + ((lane >> 4) << 3)) * 2;
    uint32_t bBase;
    if (BTRANS)
        bBase = ((uint32_t)(lane & 15) * 136 + wn + ((lane >> 4) << 3)) * 2;
    else
        bBase = ((uint32_t)(wn + (lane & 7) + ((lane >> 4) & 1) * 8) * 24 +
                 ((lane >> 3) & 1) * 8) * 2;

    load_stage(0, 0);

    for (int c = 0; c < NC; c++) {
        if (c + 1 < NC) { load_stage((c + 1) & 1, (c + 1) * 16); CP_WAIT1; }
        else            { CP_WAIT0; }
        __syncthreads();

        const uint32_t bufb = sb + (c & 1) * STG;
        const uint32_t aH = bufb + AHO + aBase;
        const uint32_t aL = aH + ALOFF;
        const uint32_t bH = bufb + BHO + bBase;
        const uint32_t bL = bH + BLOFF;

        uint32_t fAh[4][4], fAl[4][4];
#pragma unroll
        for (int mi = 0; mi < 4; mi++) {
            ldsm4(fAh[mi], aH + mi * 768);
            ldsm4(fAl[mi], aL + mi * 768);
        }
        uint32_t fBh[2][4], fBl[2][4];
#pragma unroll
        for (int p = 0; p < 2; p++) {
            const uint32_t off = BTRANS ? (uint32_t)(p * 32) : (uint32_t)(p * 768);
            if (BTRANS) { ldsm4t(fBh[p], bH + off); ldsm4t(fBl[p], bL + off); }
            else        { ldsm4 (fBh[p], bH + off); ldsm4 (fBl[p], bL + off); }
        }

#pragma unroll
        for (int mi = 0; mi < 4; mi++)
#pragma unroll
            for (int p = 0; p < 2; p++)
#pragma unroll
                for (int j = 0; j < 2; j++) {
                    float* d = acc[mi][2 * p + j];
                    mma_bf16(d, fAh[mi], &fBh[p][2 * j]);
                    mma_bf16(d, fAh[mi], &fBl[p][2 * j]);
                    mma_bf16(d, fAl[mi], &fBh[p][2 * j]);
                }
        __syncthreads();
    }

    // -- epilogue ------------------------------------------------------------
#pragma unroll
    for (int mi = 0; mi < 4; mi++) {
        const int rowb = m0 + wm + mi * 16 + (lane >> 2);
#pragma unroll
        for (int half = 0; half < 2; half++) {
            const int r = rowb + half * 8;
            float bv = 0.f;
            if (GID == 1 || GID == 5) bv = bias[r];
#pragma unroll
            for (int ni = 0; ni < 4; ni++) {
                const int col = n0 + wn + ni * 8 + (lane & 3) * 2;
                float v0 = acc[mi][ni][half * 2 + 0] + bv;
                float v1 = acc[mi][ni][half * 2 + 1] + bv;
                if (GID == 2) {
                    float2 fv = make_float2(v0, v1);
                    *(float2*)&g_S[(size_t)bz * CH * CH + (size_t)r * CH + col] = fv;
                } else if (GID == 5) {
                    if (col < NPIX) {
                        float2 fv = make_float2(v0, v1);
                        *(float2*)&outF[(size_t)bz * CH * NPIX + (size_t)r * NPIX + col] = fv;
                    }
                } else {
                    if (GID == 1 && col >= NPIX) { v0 = 0.f; v1 = 0.f; }
                    __nv_bfloat16 h0, l0, h1, l1;
                    split2(v0, h0, l0);
                    split2(v1, h1, l1);
                    const size_t o = (size_t)bz * CH * NP + (size_t)r * NP + col;
                    __nv_bfloat162 hv; hv.x = h0; hv.y = h1;
                    __nv_bfloat162 lv; lv.x = l0; lv.y = l1;
                    if (GID == 1) { *(__nv_bfloat162*)&g_qh[o] = hv; *(__nv_bfloat162*)&g_ql[o] = lv; }
                    else          { *(__nv_bfloat162*)&g_th[o] = hv; *(__nv_bfloat162*)&g_tl[o] = lv; }
                }
            }
        }
    }
}

// ---------------------------------------------------------------------------
// prep: split W / x into bf16 hi+lo (x goes into padded [C][NP], pads = 0)
// ---------------------------------------------------------------------------
__global__ void prep_w(const float* __restrict__ W)
{
    const int i = blockIdx.x * 256 + threadIdx.x;
    split2(W[i], g_Wh[i], g_Wl[i]);
}

__global__ void prep_x(const float* __restrict__ x)
{
    const size_t i = (size_t)blockIdx.x * 256 + threadIdx.x;  // over NB*CH*NP
    const int    n = (int)(i % NP);
    const size_t bc = i / NP;
    float v = 0.f;
    if (n < NPIX) v = x[bc * NPIX + n];
    split2(v, g_Xh[i], g_Xl[i]);
}

// ---------------------------------------------------------------------------
// softmax over 256-wide rows of g_S -> split-bf16 attn
// ---------------------------------------------------------------------------
__global__ void softmax_split()
{
    const size_t row = blockIdx.x;
    const float* p = g_S + row * CH;
    const int t = threadIdx.x;

    __shared__ float redm[8];
    __shared__ float reds[8];

    const float v = p[t];
    float m = v;
#pragma unroll
    for (int o = 16; o > 0; o >>= 1)
        m = fmaxf(m, __shfl_xor_sync(0xffffffffu, m, o));
    if ((t & 31) == 0) redm[t >> 5] = m;
    __syncthreads();
    float mx = redm[0];
#pragma unroll
    for (int i = 1; i < 8; i++) mx = fmaxf(mx, redm[i]);

    const float e = __expf(v - mx);
    float s = e;
#pragma unroll
    for (int o = 16; o > 0; o >>= 1)
        s += __shfl_xor_sync(0xffffffffu, s, o);
    if ((t & 31) == 0) reds[t >> 5] = s;
    __syncthreads();
    float sum = reds[0];
#pragma unroll
    for (int i = 1; i < 8; i++) sum += reds[i];

    const float a = e / sum;
    split2(a, g_Ah[row * CH + t], g_Al[row * CH + t]);
}

// ---------------------------------------------------------------------------
extern "C" void kernel_launch(void* const* d_in, const int* in_sizes, int n_in,
                              void* d_out, int out_size)
{
    const float* x    = (const float*)d_in[0];  // [32,256,56,56]
    const float* W    = (const float*)d_in[1];  // [256,256]
    const float* bias = (const float*)d_in[2];  // [256]
    float* out = (float*)d_out;                 // [32,256,56,56]

    const dim3 gBig(NP / 128, CH / 128, NB);    // 25 x 2 x 32
    const dim3 gSc (CH / 128, CH / 128, NB);    // 2 x 2 x 32

    prep_w<<<CH * CH / 256, 256>>>(W);
    prep_x<<<(unsigned)(((size_t)NB * CH * NP) / 256), 256>>>(x);
    gemm_mma<1><<<gBig, 256>>>(bias, nullptr);   // q = W@x + b  (split, pads zeroed)
    gemm_mma<2><<<gSc, 256>>>(nullptr, nullptr); // S = q@q^T    (fp32)
    softmax_split<<<NB * CH, 256>>>();           // attn (split)
    gemm_mma<4><<<gBig, 256>>>(nullptr, nullptr);// t = attn@q   (split)
    gemm_mma<5><<<gBig, 256>>>(bias, out);       // out = W@t + b
}

// round 6
// speedup vs baseline: 2.2185x; 1.1134x over previous
#include <cuda_runtime.h>
#include <cuda_bf16.h>
#include <cstdint>

#define CH    256
#define NPIX  3136
#define NP    3200
#define NB    32
#define KSPL  4          // split-K factor for the scores GEMM
#define KSL   (NP / KSPL)   // 800

// ---------------------------------------------------------------------------
// Device scratch (no allocations). All row-major, no transposed copies needed.
// ---------------------------------------------------------------------------
__device__ __nv_bfloat16 g_Wh[CH * CH], g_Wl[CH * CH];
__device__ __nv_bfloat16 g_Xh[(size_t)NB * CH * NP], g_Xl[(size_t)NB * CH * NP];  // x split
__device__ __nv_bfloat16 g_qh[(size_t)NB * CH * NP], g_ql[(size_t)NB * CH * NP];  // q split
__device__ float         g_Sp[(size_t)NB * KSPL * CH * CH];                       // score partials
__device__ __nv_bfloat16 g_Ah[(size_t)NB * CH * CH], g_Al[(size_t)NB * CH * CH];  // attn split
__device__ __nv_bfloat16 g_th[(size_t)NB * CH * NP], g_tl[(size_t)NB * CH * NP];  // t split

// ---------------------------------------------------------------------------
// PTX helpers (sm_80+ features only: mma.sync, ldmatrix, cp.async)
// ---------------------------------------------------------------------------
__device__ __forceinline__ void ldsm4(uint32_t* r, uint32_t a) {
    asm volatile("ldmatrix.sync.aligned.m8n8.x4.shared.b16 {%0,%1,%2,%3}, [%4];"
                 : "=r"(r[0]), "=r"(r[1]), "=r"(r[2]), "=r"(r[3]) : "r"(a));
}
__device__ __forceinline__ void ldsm4t(uint32_t* r, uint32_t a) {
    asm volatile("ldmatrix.sync.aligned.m8n8.x4.trans.shared.b16 {%0,%1,%2,%3}, [%4];"
                 : "=r"(r[0]), "=r"(r[1]), "=r"(r[2]), "=r"(r[3]) : "r"(a));
}
__device__ __forceinline__ void mma_bf16(float* c, const uint32_t* a, const uint32_t* b) {
    asm volatile("mma.sync.aligned.m16n8k16.row.col.f32.bf16.bf16.f32 "
                 "{%0,%1,%2,%3}, {%4,%5,%6,%7}, {%8,%9}, {%0,%1,%2,%3};"
                 : "+f"(c[0]), "+f"(c[1]), "+f"(c[2]), "+f"(c[3])
                 : "r"(a[0]), "r"(a[1]), "r"(a[2]), "r"(a[3]), "r"(b[0]), "r"(b[1]));
}
__device__ __forceinline__ void cpa(uint32_t d, const void* s) {
    uint64_t g;
    asm("cvta.to.global.u64 %0, %1;" : "=l"(g) : "l"(s));
    asm volatile("cp.async.cg.shared.global [%0], [%1], 16;" :: "r"(d), "l"(g) : "memory");
}
#define CP_COMMIT asm volatile("cp.async.commit_group;" ::: "memory")
#define CP_WAIT1  asm volatile("cp.async.wait_group 1;" ::: "memory")
#define CP_WAIT0  asm volatile("cp.async.wait_group 0;" ::: "memory")

__device__ __forceinline__ uint32_t smem_u32(const void* p) {
    uint32_t a;
    asm("{ .reg .u64 t; cvta.to.shared.u64 t, %1; cvt.u32.u64 %0, t; }" : "=r"(a) : "l"(p));
    return a;
}
__device__ __forceinline__ void split2(float v, __nv_bfloat16& h, __nv_bfloat16& l) {
    h = __float2bfloat16(v);
    l = __float2bfloat16(v - __bfloat162float(h));
}

// ---------------------------------------------------------------------------
// Unified split-bf16 tensor-core GEMM.
//   GID 1: q   = W @ x    (+bias, zero n-pads)  M=256 N=NP  K=256   B trans
//   GID 2: Sp  = q @ q^T  (fp32, split-K=4)     M=256 N=256 K=800   B non-trans
//   GID 4: t   = attn @ q                       M=256 N=NP  K=256   B trans
//   GID 5: out = W @ t    (+bias, fp32 out)     M=256 N=NP  K=256   B trans
// BM=128 BN=128 BK=16, 256 thr (8 warps 2x4), warp tile 64x32.
// Static SMEM 48KB: 2 stages x (Ah|Al @stride 24el, Bh|Bl @BHO).
// ---------------------------------------------------------------------------
#define STG   24576
#define AHO   0
#define ALOFF 6144
#define BHO   12288

template<int GID>
__global__ __launch_bounds__(256, 2)
void gemm_mma(const float* __restrict__ bias, float* __restrict__ outF)
{
    constexpr bool BTRANS = (GID != 2);
    constexpr int  KLEN   = (GID == 2) ? KSL : CH;    // K per CTA
    constexpr int  NC     = KLEN / 16;
    constexpr int  BLOFF  = BTRANS ? 4352 : 6144;     // B tile bytes per h/l

    __shared__ __align__(256) char smem[49152];
    const uint32_t sb = smem_u32(smem);

    const int tid  = threadIdx.x;
    const int lane = tid & 31;
    const int wid  = tid >> 5;
    const int wm   = (wid >> 2) * 64;
    const int wn   = (wid & 3) * 32;
    const int bz   = (GID == 2) ? (blockIdx.z >> 2) : blockIdx.z;
    const int kbase = (GID == 2) ? (blockIdx.z & 3) * KSL : 0;
    const int n0   = blockIdx.x * 128;
    const int m0   = blockIdx.y * 128;

    const __nv_bfloat16 *Ah, *Al, *Bh, *Bl;
    if (GID == 1) {
        Ah = g_Wh;  Al = g_Wl;
        Bh = g_Xh + (size_t)bz * CH * NP;  Bl = g_Xl + (size_t)bz * CH * NP;
    } else if (GID == 2) {
        Ah = g_qh + (size_t)bz * CH * NP;  Al = g_ql + (size_t)bz * CH * NP;
        Bh = Ah;  Bl = Al;
    } else if (GID == 4) {
        Ah = g_Ah + (size_t)bz * CH * CH;  Al = g_Al + (size_t)bz * CH * CH;
        Bh = g_qh + (size_t)bz * CH * NP;  Bl = g_ql + (size_t)bz * CH * NP;
    } else {
        Ah = g_Wh;  Al = g_Wl;
        Bh = g_th + (size_t)bz * CH * NP;  Bl = g_tl + (size_t)bz * CH * NP;
    }
    constexpr int LDAB = (GID == 2) ? NP : ((GID == 4) ? CH : CH);  // A row stride
    constexpr int LDB  = (GID == 2) ? NP : NP;                       // B row stride
    // (GID 1/5: A=W has stride CH; B arrays stride NP.  GID 4: A stride CH, B stride NP.
    //  GID 2: both stride NP.)
    constexpr int LDA = (GID == 2) ? NP : CH;

    float acc[4][4][4];
#pragma unroll
    for (int mi = 0; mi < 4; mi++)
#pragma unroll
        for (int ni = 0; ni < 4; ni++)
#pragma unroll
            for (int r = 0; r < 4; r++) acc[mi][ni][r] = 0.f;

    // -- stage loader: 4 x cp.async(16B) per thread --------------------------
    auto load_stage = [&](int buf, int k0) {
        const uint32_t base = sb + buf * STG;
        {   // A: 128 rows x 16el (2 chunks), stride 24el(48B)
            const int row = tid >> 1, g = tid & 1;
            const uint32_t d = base + AHO + row * 48 + g * 16;
            const size_t  so = (size_t)(m0 + row) * LDA + k0 + g * 8;
            cpa(d,          Ah + so);
            cpa(d + ALOFF,  Al + so);
        }
        if (BTRANS) {  // B: [k=16][n=128] rows, stride 136el(272B)
            const int row = tid >> 4, g = tid & 15;
            const uint32_t d = base + BHO + row * 272 + g * 16;
            const size_t  so = (size_t)(k0 + row) * LDB + n0 + g * 8;
            cpa(d,          Bh + so);
            cpa(d + BLOFF,  Bl + so);
        } else {       // B: [n=128][k=16] rows, stride 24el(48B)
            const int row = tid >> 1, g = tid & 1;
            const uint32_t d = base + BHO + row * 48 + g * 16;
            const size_t  so = (size_t)(n0 + row) * LDB + k0 + g * 8;
            cpa(d,          Bh + so);
            cpa(d + BLOFF,  Bl + so);
        }
        CP_COMMIT;
    };

    // ldmatrix base offsets (element units -> bytes)
    const uint32_t aBase = ((uint32_t)(wm + (lane & 15)) * 24 + ((lane >> 4) << 3)) * 2;
    uint32_t bBase;
    if (BTRANS)
        bBase = ((uint32_t)(lane & 15) * 136 + wn + ((lane >> 4) << 3)) * 2;
    else
        bBase = ((uint32_t)(wn + (lane & 7) + ((lane >> 4) & 1) * 8) * 24 +
                 ((lane >> 3) & 1) * 8) * 2;

    load_stage(0, kbase);

    for (int c = 0; c < NC; c++) {
        if (c + 1 < NC) { load_stage((c + 1) & 1, kbase + (c + 1) * 16); CP_WAIT1; }
        else            { CP_WAIT0; }
        __syncthreads();

        const uint32_t bufb = sb + (c & 1) * STG;
        const uint32_t aH = bufb + AHO + aBase;
        const uint32_t aL = aH + ALOFF;
        const uint32_t bH = bufb + BHO + bBase;
        const uint32_t bL = bH + BLOFF;

        uint32_t fAh[4][4], fAl[4][4];
#pragma unroll
        for (int mi = 0; mi < 4; mi++) {
            ldsm4(fAh[mi], aH + mi * 768);
            ldsm4(fAl[mi], aL + mi * 768);
        }
        uint32_t fBh[2][4], fBl[2][4];
#pragma unroll
        for (int p = 0; p < 2; p++) {
            const uint32_t off = BTRANS ? (uint32_t)(p * 32) : (uint32_t)(p * 768);
            if (BTRANS) { ldsm4t(fBh[p], bH + off); ldsm4t(fBl[p], bL + off); }
            else        { ldsm4 (fBh[p], bH + off); ldsm4 (fBl[p], bL + off); }
        }

#pragma unroll
        for (int mi = 0; mi < 4; mi++)
#pragma unroll
            for (int p = 0; p < 2; p++)
#pragma unroll
                for (int j = 0; j < 2; j++) {
                    float* d = acc[mi][2 * p + j];
                    mma_bf16(d, fAh[mi], &fBh[p][2 * j]);
                    mma_bf16(d, fAh[mi], &fBl[p][2 * j]);
                    mma_bf16(d, fAl[mi], &fBh[p][2 * j]);
                }
        __syncthreads();
    }

    // -- epilogue ------------------------------------------------------------
#pragma unroll
    for (int mi = 0; mi < 4; mi++) {
        const int rowb = m0 + wm + mi * 16 + (lane >> 2);
#pragma unroll
        for (int half = 0; half < 2; half++) {
            const int r = rowb + half * 8;
            float bv = 0.f;
            if (GID == 1 || GID == 5) bv = bias[r];
#pragma unroll
            for (int ni = 0; ni < 4; ni++) {
                const int col = n0 + wn + ni * 8 + (lane & 3) * 2;
                float v0 = acc[mi][ni][half * 2 + 0] + bv;
                float v1 = acc[mi][ni][half * 2 + 1] + bv;
                if (GID == 2) {
                    float2 fv = make_float2(v0, v1);
                    *(float2*)&g_Sp[(size_t)blockIdx.z * CH * CH + (size_t)r * CH + col] = fv;
                } else if (GID == 5) {
                    if (col < NPIX) {
                        float2 fv = make_float2(v0, v1);
                        *(float2*)&outF[(size_t)bz * CH * NPIX + (size_t)r * NPIX + col] = fv;
                    }
                } else {
                    if (GID == 1 && col >= NPIX) { v0 = 0.f; v1 = 0.f; }
                    __nv_bfloat16 h0, l0, h1, l1;
                    split2(v0, h0, l0);
                    split2(v1, h1, l1);
                    const size_t o = (size_t)bz * CH * NP + (size_t)r * NP + col;
                    __nv_bfloat162 hv; hv.x = h0; hv.y = h1;
                    __nv_bfloat162 lv; lv.x = l0; lv.y = l1;
                    if (GID == 1) { *(__nv_bfloat162*)&g_qh[o] = hv; *(__nv_bfloat162*)&g_ql[o] = lv; }
                    else          { *(__nv_bfloat162*)&g_th[o] = hv; *(__nv_bfloat162*)&g_tl[o] = lv; }
                }
            }
        }
    }
}

// ---------------------------------------------------------------------------
// prep: split W / x into bf16 hi+lo (x goes into padded [C][NP], pads = 0)
// ---------------------------------------------------------------------------
__global__ void prep_w(const float* __restrict__ W)
{
    const int i = blockIdx.x * 256 + threadIdx.x;
    split2(W[i], g_Wh[i], g_Wl[i]);
}

// one block (400 thr) per [b][c] row; thread t handles n = t*8 .. t*8+7
// NPIX = 392*8, so groups 0..391 are fully in-bounds, 392..399 fully pad.
__global__ __launch_bounds__(400)
void prep_x(const float* __restrict__ x)
{
    const size_t bc = blockIdx.x;
    const int    n0 = threadIdx.x * 8;

    __nv_bfloat16 h[8], l[8];
    if (n0 < NPIX) {
        const float4 v0 = *(const float4*)(x + bc * NPIX + n0);
        const float4 v1 = *(const float4*)(x + bc * NPIX + n0 + 4);
        split2(v0.x, h[0], l[0]); split2(v0.y, h[1], l[1]);
        split2(v0.z, h[2], l[2]); split2(v0.w, h[3], l[3]);
        split2(v1.x, h[4], l[4]); split2(v1.y, h[5], l[5]);
        split2(v1.z, h[6], l[6]); split2(v1.w, h[7], l[7]);
    } else {
#pragma unroll
        for (int i = 0; i < 8; i++) { h[i] = __float2bfloat16(0.f); l[i] = h[i]; }
    }
    const size_t o = bc * NP + n0;
    *(uint4*)&g_Xh[o] = *(uint4*)h;
    *(uint4*)&g_Xl[o] = *(uint4*)l;
}

// ---------------------------------------------------------------------------
// softmax over 256-wide rows: sum the KSPL score partials, then softmax,
// write attn as split bf16.  One block (256 thr) per (b, row).
// ---------------------------------------------------------------------------
__global__ void softmax_split()
{
    const int b = blockIdx.x >> 8;
    const int r = blockIdx.x & 255;
    const int t = threadIdx.x;

    float v = 0.f;
#pragma unroll
    for (int s = 0; s < KSPL; s++)
        v += g_Sp[(size_t)(b * KSPL + s) * CH * CH + (size_t)r * CH + t];

    __shared__ float redm[8];
    __shared__ float reds[8];

    float m = v;
#pragma unroll
    for (int o = 16; o > 0; o >>= 1)
        m = fmaxf(m, __shfl_xor_sync(0xffffffffu, m, o));
    if ((t & 31) == 0) redm[t >> 5] = m;
    __syncthreads();
    float mx = redm[0];
#pragma unroll
    for (int i = 1; i < 8; i++) mx = fmaxf(mx, redm[i]);

    const float e = __expf(v - mx);
    float s = e;
#pragma unroll
    for (int o = 16; o > 0; o >>= 1)
        s += __shfl_xor_sync(0xffffffffu, s, o);
    if ((t & 31) == 0) reds[t >> 5] = s;
    __syncthreads();
    float sum = reds[0];
#pragma unroll
    for (int i = 1; i < 8; i++) sum += reds[i];

    const float a = e / sum;
    const size_t o = (size_t)blockIdx.x * CH + t;
    split2(a, g_Ah[o], g_Al[o]);
}

// ---------------------------------------------------------------------------
extern "C" void kernel_launch(void* const* d_in, const int* in_sizes, int n_in,
                              void* d_out, int out_size)
{
    const float* x    = (const float*)d_in[0];  // [32,256,56,56]
    const float* W    = (const float*)d_in[1];  // [256,256]
    const float* bias = (const float*)d_in[2];  // [256]
    float* out = (float*)d_out;                 // [32,256,56,56]

    const dim3 gBig(NP / 128, CH / 128, NB);        // 25 x 2 x 32
    const dim3 gSc (CH / 128, CH / 128, NB * KSPL); // 2 x 2 x 128  (split-K)

    prep_w<<<CH * CH / 256, 256>>>(W);
    prep_x<<<NB * CH, 400>>>(x);
    gemm_mma<1><<<gBig, 256>>>(bias, nullptr);   // q = W@x + b  (split, pads zeroed)
    gemm_mma<2><<<gSc, 256>>>(nullptr, nullptr); // Sp = q@q^T partials (fp32)
    softmax_split<<<NB * CH, 256>>>();           // sum partials + softmax -> attn
    gemm_mma<4><<<gBig, 256>>>(nullptr, nullptr);// t = attn@q   (split)
    gemm_mma<5><<<gBig, 256>>>(bias, out);       // out = W@t + b
}